// round 16
// baseline (speedup 1.0000x reference)
#include <cuda_runtime.h>
#include <cuda_bf16.h>
#include <cstdint>

typedef unsigned int u32;

#define T_ 200
#define S_ 20
#define BT_ 16
#define KS1 27              // K1=432 = 3*144, 16 per step
#define KS2 36              // K2=576 = 3*192
#define KP1 456             // B1 row stride (elems)
#define KP2 584             // B2 row stride

#define O_B1 0
#define SZ_B1 (BT_*KP1*2)
#define O_B2 (O_B1+SZ_B1)
#define SZ_B2 (BT_*KP2*2)
#define O_H2F (O_B2+SZ_B2)
#define O_DS  (O_H2F+64*17*4)
#define SMEMB (O_DS+BT_*33*4)

__device__ __align__(16) unsigned char dA1[KS1*8*4*512];
__device__ __align__(16) unsigned char dA2[KS2*8*2*512];
__device__ float dBi1[512];
__device__ float dBi2[256];

__device__ __forceinline__ float th_(float x){float y;asm("tanh.approx.f32 %0,%1;":"=f"(y):"f"(x));return y;}
__device__ __forceinline__ float sg_(float x){return fmaf(0.5f,th_(0.5f*x),0.5f);}

__device__ __forceinline__ void mma_(float* d,const uint4 a,u32 b0,u32 b1){
    asm volatile("mma.sync.aligned.m16n8k16.row.col.f32.bf16.bf16.f32 "
        "{%0,%1,%2,%3},{%4,%5,%6,%7},{%8,%9},{%0,%1,%2,%3};"
        :"+f"(d[0]),"+f"(d[1]),"+f"(d[2]),"+f"(d[3])
        :"r"(a.x),"r"(a.y),"r"(a.z),"r"(a.w),"r"(b0),"r"(b1));
}
__device__ __forceinline__ void put3(unsigned char* B,int kpad,int n,int k3,float v){
    __nv_bfloat16 h=__float2bfloat16(v);
    __nv_bfloat16 l=__float2bfloat16(v-__bfloat162float(h));
    __nv_bfloat16* p=(__nv_bfloat16*)(B+(size_t)n*kpad*2)+k3;
    p[0]=h; p[1]=l; p[2]=h;
}
__device__ __forceinline__ void loadA1(uint4* d,int ks,int wid,int lane){
    const uint4* p=(const uint4*)dA1+(size_t)((ks*8+wid)*4)*32+lane;
#pragma unroll
    for(int mt=0;mt<4;mt++) d[mt]=p[mt*32];
}
__device__ __forceinline__ void loadA2(uint4* d,int ks,int wid,int lane){
    const uint4* p=(const uint4*)dA2+(size_t)((ks*8+wid)*2)*32+lane;
    d[0]=p[0]; d[1]=p[32];
}
__device__ __forceinline__ void bfrag(const unsigned char* Bb,int kpad,int ks,int gq,int t,u32* b0,u32* b1){
#pragma unroll
    for(int nt=0;nt<2;nt++){
        const unsigned char* p=Bb+((size_t)(nt*8+gq)*kpad+ks*16+2*t)*2;
        b0[nt]=*(const u32*)p; b1[nt]=*(const u32*)(p+16);
    }
}

// ---- prep: pack weights into HMMA A-fragment order, 3-term interleaved ----
__global__ void prep(const float* Wih1,const float* Whh1,const float* bih1,const float* bhh1,
                     const float* Wih2,const float* Whh2,const float* bih2,const float* bhh2){
    int idx=blockIdx.x*blockDim.x+threadIdx.x, st=gridDim.x*blockDim.x;
    for(int e=idx;e<KS1*8*4*256;e+=st){
        int blk=e>>3,sub=e&7,reg=sub>>1,half=sub&1;
        int lane=blk&31,mt=(blk>>5)&3,w=(blk>>7)&7,ks=blk>>10;
        int gq=lane>>2,t=lane&3;
        int lrow=gq+((reg&1)<<3), lcol=2*t+((reg>>1)<<3)+half;
        int gate=mt, unit=w*16+lrow;
        int kp=ks*16+lcol, term=kp%3, kk=kp/3;
        float wv=(kk<16)?Wih1[(gate*128+unit)*16+kk]:Whh1[(gate*128+unit)*128+kk-16];
        float hi=__bfloat162float(__float2bfloat16(wv));
        float v=(term<2)?hi:(wv-hi);
        ((__nv_bfloat16*)dA1)[blk*8+sub]=__float2bfloat16(v);
    }
    for(int e=idx;e<KS2*8*2*256;e+=st){
        int blk=e>>3,sub=e&7,reg=sub>>1,half=sub&1;
        int lane=blk&31,mt=(blk>>5)&1,w=(blk>>6)&7,ks=blk>>9;
        int gq=lane>>2,t=lane&3;
        int lrow=gq+((reg&1)<<3), lcol=2*t+((reg>>1)<<3)+half;
        int rr=mt*16+lrow, gate=rr>>3, unit=w*8+(rr&7);
        int kp=ks*16+lcol, term=kp%3, kk=kp/3;
        float wv=(kk<128)?Wih2[(gate*64+unit)*128+kk]:Whh2[(gate*64+unit)*64+kk-128];
        float hi=__bfloat162float(__float2bfloat16(wv));
        float v=(term<2)?hi:(wv-hi);
        ((__nv_bfloat16*)dA2)[blk*8+sub]=__float2bfloat16(v);
    }
    for(int i=idx;i<512;i+=st) dBi1[i]=bih1[i]+bhh1[i];
    for(int i=idx;i<256;i+=st) dBi2[i]=bih2[i]+bhh2[i];
}

// ---- main persistent HMMA kernel: 2 CTAs/SM, BT=16 ----
__global__ void __launch_bounds__(256,2) lstm_tc(
    const float* __restrict__ xh,const float* __restrict__ xf,
    const float* __restrict__ Wd,const float* __restrict__ bd,
    const float* __restrict__ Wf,const float* __restrict__ bfv,
    const float* __restrict__ ob,float* __restrict__ out){
    extern __shared__ unsigned char sm[];
    const int tid=threadIdx.x, wid=tid>>5, lane=tid&31;
    const int gq=lane>>2, t=lane&3;
    const int b0=blockIdx.x*BT_;

    for(int i=tid*16;i<SMEMB;i+=256*16) *(uint4*)(sm+i)=make_uint4(0,0,0,0);

    float bi1[2][4], bi2[4];
#pragma unroll
    for(int us=0;us<2;us++)
#pragma unroll
        for(int gt=0;gt<4;gt++) bi1[us][gt]=dBi1[gt*128+wid*16+gq+us*8];
#pragma unroll
    for(int gt=0;gt<4;gt++) bi2[gt]=dBi2[gt*64+wid*8+gq];

    float c1r[8], c2r[4];
#pragma unroll
    for(int j=0;j<8;j++) c1r[j]=0.f;
#pragma unroll
    for(int j=0;j<4;j++) c2r[j]=0.f;
    __syncthreads();

    for(int ts=0;ts<T_+S_;ts++){
        const int dec=ts>=T_; const int tt0=dec?ts-T_:ts;
        if(!dec){
            int bt=tid>>4, f=tid&15;
            put3(sm+O_B1,KP1,bt,3*f, xh[(size_t)(b0+bt)*T_*16+(size_t)tt0*16+f]);
        } else if(tid<224){
            int f=tid%14, bt=tid/14;
            put3(sm+O_B1,KP1,bt,3*f, xf[(size_t)(b0+bt)*S_*14+(size_t)tt0*14+f]);
        }
        __syncthreads();

        // ---- layer 1: M=512, N=16, 27 k-steps ----
        float ac[4][8];
#pragma unroll
        for(int m=0;m<4;m++)
#pragma unroll
            for(int j2=0;j2<8;j2++) ac[m][j2]=0.f;
        {
            uint4 A[4],N[4];
            loadA1(A,0,wid,lane); loadA1(N,1,wid,lane);
            u32 b0f[2],b1f[2];
#pragma unroll 1
            for(int ks=0;ks<26;ks+=2){
                bfrag(sm+O_B1,KP1,ks,gq,t,b0f,b1f);
#pragma unroll
                for(int mt=0;mt<4;mt++)
#pragma unroll
                    for(int nt=0;nt<2;nt++) mma_(&ac[mt][nt*4],A[mt],b0f[nt],b1f[nt]);
                if(ks+2<KS1) loadA1(A,ks+2,wid,lane);
                bfrag(sm+O_B1,KP1,ks+1,gq,t,b0f,b1f);
#pragma unroll
                for(int mt=0;mt<4;mt++)
#pragma unroll
                    for(int nt=0;nt<2;nt++) mma_(&ac[mt][nt*4],N[mt],b0f[nt],b1f[nt]);
                if(ks+3<KS1) loadA1(N,ks+3,wid,lane);
            }
            bfrag(sm+O_B1,KP1,26,gq,t,b0f,b1f);
#pragma unroll
            for(int mt=0;mt<4;mt++)
#pragma unroll
                for(int nt=0;nt<2;nt++) mma_(&ac[mt][nt*4],A[mt],b0f[nt],b1f[nt]);
        }
        __syncthreads();
        // epilogue 1
#pragma unroll
        for(int us=0;us<2;us++)
#pragma unroll
            for(int nt=0;nt<2;nt++)
#pragma unroll
                for(int j=0;j<2;j++){
                    int ci=us*4+nt*2+j;
                    float gi=ac[0][nt*4+us*2+j]+bi1[us][0];
                    float gf=ac[1][nt*4+us*2+j]+bi1[us][1];
                    float gg=ac[2][nt*4+us*2+j]+bi1[us][2];
                    float go=ac[3][nt*4+us*2+j]+bi1[us][3];
                    float c=sg_(gf)*c1r[ci]+sg_(gi)*th_(gg); c1r[ci]=c;
                    float h=sg_(go)*th_(c);
                    int unit=wid*16+gq+us*8, n=nt*8+2*t+j;
                    put3(sm+O_B1,KP1,n,3*(16+unit),h);
                    put3(sm+O_B2,KP2,n,3*unit,h);
                }
        __syncthreads();

        // ---- layer 2: M=256, N=16, 36 k-steps ----
        float ac2[2][8];
#pragma unroll
        for(int m=0;m<2;m++)
#pragma unroll
            for(int j2=0;j2<8;j2++) ac2[m][j2]=0.f;
        {
            uint4 A[2],N[2];
            loadA2(A,0,wid,lane); loadA2(N,1,wid,lane);
            u32 b0f[2],b1f[2];
#pragma unroll 1
            for(int ks=0;ks<KS2;ks+=2){
                bfrag(sm+O_B2,KP2,ks,gq,t,b0f,b1f);
#pragma unroll
                for(int mt=0;mt<2;mt++)
#pragma unroll
                    for(int nt=0;nt<2;nt++) mma_(&ac2[mt][nt*4],A[mt],b0f[nt],b1f[nt]);
                if(ks+2<KS2) loadA2(A,ks+2,wid,lane);
                bfrag(sm+O_B2,KP2,ks+1,gq,t,b0f,b1f);
#pragma unroll
                for(int mt=0;mt<2;mt++)
#pragma unroll
                    for(int nt=0;nt<2;nt++) mma_(&ac2[mt][nt*4],N[mt],b0f[nt],b1f[nt]);
                if(ks+3<KS2) loadA2(N,ks+3,wid,lane);
            }
        }
        __syncthreads();
        // epilogue 2: unit u2=wid*8+gq
#pragma unroll
        for(int nt=0;nt<2;nt++)
#pragma unroll
            for(int j=0;j<2;j++){
                int ci=nt*2+j;
                float gi=ac2[0][nt*4+j]  +bi2[0];
                float gf=ac2[0][nt*4+2+j]+bi2[1];
                float gg=ac2[1][nt*4+j]  +bi2[2];
                float go=ac2[1][nt*4+2+j]+bi2[3];
                float c=sg_(gf)*c2r[ci]+sg_(gi)*th_(gg); c2r[ci]=c;
                float h=sg_(go)*th_(c);
                int u2=wid*8+gq, n=nt*8+2*t+j;
                put3(sm+O_B2,KP2,n,3*(128+u2),h);
                if(dec) ((float*)(sm+O_H2F))[u2*17+n]=h;
            }
        __syncthreads();

        if(dec){
            {
                int du=tid&31, g8=tid>>5;   // batches 2*g8, 2*g8+1
                const float* h2f=(const float*)(sm+O_H2F);
                float a0=0.f,a1=0.f;
#pragma unroll 4
                for(int k=0;k<64;k++){
                    float w=Wd[du*64+k];
                    const float* r=h2f+k*17+g8*2;
                    a0=fmaf(w,r[0],a0); a1=fmaf(w,r[1],a1);
                }
                float bdv=bd[du];
                float* ds=(float*)(sm+O_DS);
                ds[(g8*2+0)*33+du]=fmaxf(a0+bdv,0.f);
                ds[(g8*2+1)*33+du]=fmaxf(a1+bdv,0.f);
            }
            __syncthreads();
            if(tid<32){
                int bt=tid>>1, t2=tid&1;
                const float* ds=(const float*)(sm+O_DS);
                float acc=0.f;
#pragma unroll
                for(int k=0;k<32;k++) acc=fmaf(ds[bt*33+k],Wf[t2*32+k],acc);
                float pr=acc+bfv[t2]+ob[t2];
                out[(size_t)(b0+bt)*S_*2+(size_t)tt0*2+t2]=pr;
                put3(sm+O_B1,KP1,bt,3*(14+t2),pr);
            }
            __syncthreads();
        }
    }
}

extern "C" void kernel_launch(void* const* d_in, const int* in_sizes, int n_in,
                              void* d_out, int out_size){
    (void)in_sizes;(void)n_in;(void)out_size;
    prep<<<64,256>>>((const float*)d_in[2],(const float*)d_in[3],
                     (const float*)d_in[4],(const float*)d_in[5],
                     (const float*)d_in[6],(const float*)d_in[7],
                     (const float*)d_in[8],(const float*)d_in[9]);
    cudaFuncSetAttribute(lstm_tc,cudaFuncAttributeMaxDynamicSharedMemorySize,SMEMB);
    lstm_tc<<<256,256,SMEMB>>>((const float*)d_in[0],(const float*)d_in[1],
                               (const float*)d_in[10],(const float*)d_in[11],
                               (const float*)d_in[12],(const float*)d_in[13],
                               (const float*)d_in[14],(float*)d_out);
}

// round 17
// speedup vs baseline: 1.0185x; 1.0185x over previous
#include <cuda_runtime.h>
#include <cuda_bf16.h>
#include <cstdint>

typedef unsigned int u32;

#define T_ 200
#define S_ 20
#define BT_ 32
#define KS1 27              // K1=432 = 3*144
#define KS2 36              // K2=576 = 3*192
#define KP1 456
#define KP2 584
#define DEPTH 5

#define O_B1 0
#define SZ_B1 (BT_*KP1*2)           // 29184
#define O_B2 (O_B1+SZ_B1)
#define SZ_B2 (BT_*KP2*2)           // 37376
#define O_H2F (O_B2+SZ_B2)          // 66560
#define O_DS  (O_H2F+64*33*4)       // 75008
#define O_SA  (O_DS+32*33*4)        // 79232
#define SMEMB (O_SA+DEPTH*8*2048)   // 161152

__device__ __align__(16) unsigned char dA1[KS1*8*4*512];
__device__ __align__(16) unsigned char dA2[KS2*8*2*512];
__device__ float dBi1[512];
__device__ float dBi2[256];

__device__ __forceinline__ float th_(float x){float y;asm("tanh.approx.f32 %0,%1;":"=f"(y):"f"(x));return y;}
__device__ __forceinline__ float sg_(float x){return fmaf(0.5f,th_(0.5f*x),0.5f);}

__device__ __forceinline__ u32 s2u(const void* p){
    u32 a;asm("{ .reg .u64 t; cvta.to.shared.u64 t, %1; cvt.u32.u64 %0, t; }":"=r"(a):"l"(p));return a;
}
__device__ __forceinline__ void cpa16(u32 s,const void* g){
    asm volatile("cp.async.cg.shared.global [%0], [%1], 16;"::"r"(s),"l"(g):"memory");
}
#define CPCOMMIT() asm volatile("cp.async.commit_group;":::"memory")
#define CPWAIT3()  asm volatile("cp.async.wait_group 3;":::"memory")
#define CPWAIT0()  asm volatile("cp.async.wait_group 0;":::"memory")

__device__ __forceinline__ void mma_(float* d,const uint4 a,u32 b0,u32 b1){
    asm volatile("mma.sync.aligned.m16n8k16.row.col.f32.bf16.bf16.f32 "
        "{%0,%1,%2,%3},{%4,%5,%6,%7},{%8,%9},{%0,%1,%2,%3};"
        :"+f"(d[0]),"+f"(d[1]),"+f"(d[2]),"+f"(d[3])
        :"r"(a.x),"r"(a.y),"r"(a.z),"r"(a.w),"r"(b0),"r"(b1));
}
__device__ __forceinline__ void put3(unsigned char* B,int kpad,int n,int k3,float v){
    __nv_bfloat16 h=__float2bfloat16(v);
    __nv_bfloat16 l=__float2bfloat16(v-__bfloat162float(h));
    __nv_bfloat16* p=(__nv_bfloat16*)(B+(size_t)n*kpad*2)+k3;
    p[0]=h; p[1]=l; p[2]=h;
}
// async-copy one k-step warp slice (2KB) of layer1 A into stage st
__device__ __forceinline__ void cp1(u32 saw,int st,int ks,int wid,int lane){
    u32 s=saw+st*16384+lane*16;
    const unsigned char* g=dA1+((size_t)(ks*8+wid))*2048+lane*16;
#pragma unroll
    for(int mt=0;mt<4;mt++) cpa16(s+mt*512,g+mt*512);
}
__device__ __forceinline__ void cp2(u32 saw,int st,int ks,int wid,int lane){
    u32 s=saw+st*8192+lane*16;
    const unsigned char* g=dA2+((size_t)(ks*8+wid))*1024+lane*16;
    cpa16(s,g); cpa16(s+512,g+512);
}
__device__ __forceinline__ void ldA1(uint4* d,const unsigned char* sm,int st,int wid,int lane){
    const uint4* p=(const uint4*)(sm+O_SA+(size_t)(st*8+wid)*2048)+lane;
#pragma unroll
    for(int mt=0;mt<4;mt++) d[mt]=p[mt*32];
}
__device__ __forceinline__ void ldA2(uint4* d,const unsigned char* sm,int st,int wid,int lane){
    const uint4* p=(const uint4*)(sm+O_SA+(size_t)(st*8+wid)*1024)+lane;
    d[0]=p[0]; d[1]=p[32];
}
__device__ __forceinline__ void bfrag(const unsigned char* Bb,int kpad,int ks,int gq,int t,u32* b0,u32* b1){
#pragma unroll
    for(int nt=0;nt<4;nt++){
        const unsigned char* p=Bb+((size_t)(nt*8+gq)*kpad+ks*16+2*t)*2;
        b0[nt]=*(const u32*)p; b1[nt]=*(const u32*)(p+16);
    }
}

// ---- prep: identical packing to R15 ----
__global__ void prep(const float* Wih1,const float* Whh1,const float* bih1,const float* bhh1,
                     const float* Wih2,const float* Whh2,const float* bih2,const float* bhh2){
    int idx=blockIdx.x*blockDim.x+threadIdx.x, st=gridDim.x*blockDim.x;
    for(int e=idx;e<KS1*8*4*256;e+=st){
        int blk=e>>3,sub=e&7,reg=sub>>1,half=sub&1;
        int lane=blk&31,mt=(blk>>5)&3,w=(blk>>7)&7,ks=blk>>10;
        int gq=lane>>2,t=lane&3;
        int lrow=gq+((reg&1)<<3), lcol=2*t+((reg>>1)<<3)+half;
        int gate=mt, unit=w*16+lrow;
        int kp=ks*16+lcol, term=kp%3, kk=kp/3;
        float wv=(kk<16)?Wih1[(gate*128+unit)*16+kk]:Whh1[(gate*128+unit)*128+kk-16];
        float hi=__bfloat162float(__float2bfloat16(wv));
        float v=(term<2)?hi:(wv-hi);
        ((__nv_bfloat16*)dA1)[blk*8+sub]=__float2bfloat16(v);
    }
    for(int e=idx;e<KS2*8*2*256;e+=st){
        int blk=e>>3,sub=e&7,reg=sub>>1,half=sub&1;
        int lane=blk&31,mt=(blk>>5)&1,w=(blk>>6)&7,ks=blk>>9;
        int gq=lane>>2,t=lane&3;
        int lrow=gq+((reg&1)<<3), lcol=2*t+((reg>>1)<<3)+half;
        int rr=mt*16+lrow, gate=rr>>3, unit=w*8+(rr&7);
        int kp=ks*16+lcol, term=kp%3, kk=kp/3;
        float wv=(kk<128)?Wih2[(gate*64+unit)*128+kk]:Whh2[(gate*64+unit)*64+kk-128];
        float hi=__bfloat162float(__float2bfloat16(wv));
        float v=(term<2)?hi:(wv-hi);
        ((__nv_bfloat16*)dA2)[blk*8+sub]=__float2bfloat16(v);
    }
    for(int i=idx;i<512;i+=st) dBi1[i]=bih1[i]+bhh1[i];
    for(int i=idx;i<256;i+=st) dBi2[i]=bih2[i]+bhh2[i];
}

// ---- main persistent HMMA kernel, cp.async-staged weights ----
__global__ void __launch_bounds__(256,1) lstm_tc(
    const float* __restrict__ xh,const float* __restrict__ xf,
    const float* __restrict__ Wd,const float* __restrict__ bd,
    const float* __restrict__ Wf,const float* __restrict__ bfv,
    const float* __restrict__ ob,float* __restrict__ out){
    extern __shared__ unsigned char sm[];
    const int tid=threadIdx.x, wid=tid>>5, lane=tid&31;
    const int gq=lane>>2, t=lane&3;
    const int b0=blockIdx.x*BT_;
    const u32 saw1=s2u(sm)+O_SA+wid*2048;
    const u32 saw2=s2u(sm)+O_SA+wid*1024;

    for(int i=tid*16;i<SMEMB;i+=256*16) *(uint4*)(sm+i)=make_uint4(0,0,0,0);

    float bi1[2][4], bi2[4];
#pragma unroll
    for(int us=0;us<2;us++)
#pragma unroll
        for(int gt=0;gt<4;gt++) bi1[us][gt]=dBi1[gt*128+wid*16+gq+us*8];
#pragma unroll
    for(int gt=0;gt<4;gt++) bi2[gt]=dBi2[gt*64+wid*8+gq];

    float c1r[16], c2r[8];
#pragma unroll
    for(int j=0;j<16;j++) c1r[j]=0.f;
#pragma unroll
    for(int j=0;j<8;j++) c2r[j]=0.f;
    __syncthreads();

    for(int ts=0;ts<T_+S_;ts++){
        const int dec=ts>=T_; const int tt0=dec?ts-T_:ts;
        if(!dec){
#pragma unroll
            for(int r=0;r<2;r++){
                int i2=tid*2+r, bt=i2>>4, f=i2&15;
                put3(sm+O_B1,KP1,bt,3*f, xh[(size_t)(b0+bt)*T_*16+(size_t)tt0*16+f]);
            }
        } else if(tid<224){
#pragma unroll
            for(int r=0;r<2;r++){
                int i2=tid*2+r, f=i2%14, bt=i2/14;
                put3(sm+O_B1,KP1,bt,3*f, xf[(size_t)(b0+bt)*S_*14+(size_t)tt0*14+f]);
            }
        }
        __syncthreads();

        // ---- layer 1: M=512, N=32, 27 k-steps, cp.async-pipelined A ----
        float ac[4][16];
#pragma unroll
        for(int m=0;m<4;m++)
#pragma unroll
            for(int j2=0;j2<16;j2++) ac[m][j2]=0.f;
        {
#pragma unroll
            for(int d=0;d<4;d++){ cp1(saw1,d,d,wid,lane); CPCOMMIT(); }
            CPWAIT3();
            uint4 A[4],N[4];
            ldA1(A,sm,0,wid,lane);
            u32 b0f[4],b1f[4];
#pragma unroll 1
            for(int ks=0;ks<26;ks+=2){
                if(ks+4<KS1) cp1(saw1,(ks+4)%DEPTH,ks+4,wid,lane);
                CPCOMMIT(); CPWAIT3();
                ldA1(N,sm,(ks+1)%DEPTH,wid,lane);
                bfrag(sm+O_B1,KP1,ks,gq,t,b0f,b1f);
#pragma unroll
                for(int mt=0;mt<4;mt++)
#pragma unroll
                    for(int nt=0;nt<4;nt++) mma_(&ac[mt][nt*4],A[mt],b0f[nt],b1f[nt]);
                if(ks+5<KS1) cp1(saw1,(ks+5)%DEPTH,ks+5,wid,lane);
                CPCOMMIT(); CPWAIT3();
                if(ks+2<KS1) ldA1(A,sm,(ks+2)%DEPTH,wid,lane);
                bfrag(sm+O_B1,KP1,ks+1,gq,t,b0f,b1f);
#pragma unroll
                for(int mt=0;mt<4;mt++)
#pragma unroll
                    for(int nt=0;nt<4;nt++) mma_(&ac[mt][nt*4],N[mt],b0f[nt],b1f[nt]);
            }
            bfrag(sm+O_B1,KP1,26,gq,t,b0f,b1f);
#pragma unroll
            for(int mt=0;mt<4;mt++)
#pragma unroll
                for(int nt=0;nt<4;nt++) mma_(&ac[mt][nt*4],A[mt],b0f[nt],b1f[nt]);
            CPWAIT0();
        }
        __syncthreads();
        // epilogue 1
#pragma unroll
        for(int us=0;us<2;us++)
#pragma unroll
            for(int nt=0;nt<4;nt++)
#pragma unroll
                for(int j=0;j<2;j++){
                    int ci=us*8+nt*2+j;
                    float gi=ac[0][nt*4+us*2+j]+bi1[us][0];
                    float gf=ac[1][nt*4+us*2+j]+bi1[us][1];
                    float gg=ac[2][nt*4+us*2+j]+bi1[us][2];
                    float go=ac[3][nt*4+us*2+j]+bi1[us][3];
                    float c=sg_(gf)*c1r[ci]+sg_(gi)*th_(gg); c1r[ci]=c;
                    float h=sg_(go)*th_(c);
                    int unit=wid*16+gq+us*8, n=nt*8+2*t+j;
                    put3(sm+O_B1,KP1,n,3*(16+unit),h);
                    put3(sm+O_B2,KP2,n,3*unit,h);
                }
        __syncthreads();

        // ---- layer 2: M=256, N=32, 36 k-steps ----
        float ac2[2][16];
#pragma unroll
        for(int m=0;m<2;m++)
#pragma unroll
            for(int j2=0;j2<16;j2++) ac2[m][j2]=0.f;
        {
#pragma unroll
            for(int d=0;d<4;d++){ cp2(saw2,d,d,wid,lane); CPCOMMIT(); }
            CPWAIT3();
            uint4 A[2],N[2];
            ldA2(A,sm,0,wid,lane);
            u32 b0f[4],b1f[4];
#pragma unroll 1
            for(int ks=0;ks<KS2;ks+=2){
                if(ks+4<KS2) cp2(saw2,(ks+4)%DEPTH,ks+4,wid,lane);
                CPCOMMIT(); CPWAIT3();
                ldA2(N,sm,(ks+1)%DEPTH,wid,lane);
                bfrag(sm+O_B2,KP2,ks,gq,t,b0f,b1f);
#pragma unroll
                for(int mt=0;mt<2;mt++)
#pragma unroll
                    for(int nt=0;nt<4;nt++) mma_(&ac2[mt][nt*4],A[mt],b0f[nt],b1f[nt]);
                if(ks+5<KS2) cp2(saw2,(ks+5)%DEPTH,ks+5,wid,lane);
                CPCOMMIT(); CPWAIT3();
                if(ks+2<KS2) ldA2(A,sm,(ks+2)%DEPTH,wid,lane);
                bfrag(sm+O_B2,KP2,ks+1,gq,t,b0f,b1f);
#pragma unroll
                for(int mt=0;mt<2;mt++)
#pragma unroll
                    for(int nt=0;nt<4;nt++) mma_(&ac2[mt][nt*4],N[mt],b0f[nt],b1f[nt]);
            }
            CPWAIT0();
        }
        __syncthreads();
        // epilogue 2
#pragma unroll
        for(int nt=0;nt<4;nt++)
#pragma unroll
            for(int j=0;j<2;j++){
                int ci=nt*2+j;
                float gi=ac2[0][nt*4+j]  +bi2[0];
                float gf=ac2[0][nt*4+2+j]+bi2[1];
                float gg=ac2[1][nt*4+j]  +bi2[2];
                float go=ac2[1][nt*4+2+j]+bi2[3];
                float c=sg_(gf)*c2r[ci]+sg_(gi)*th_(gg); c2r[ci]=c;
                float h=sg_(go)*th_(c);
                int u2=wid*8+gq, n=nt*8+2*t+j;
                put3(sm+O_B2,KP2,n,3*(128+u2),h);
                if(dec) ((float*)(sm+O_H2F))[u2*33+n]=h;
            }
        __syncthreads();

        if(dec){
            {
                int du=tid&31, g8=tid>>5;
                const float* h2f=(const float*)(sm+O_H2F);
                float a0=0.f,a1=0.f,a2=0.f,a3=0.f;
#pragma unroll 4
                for(int k=0;k<64;k++){
                    float w=Wd[du*64+k];
                    const float* r=h2f+k*33+g8*4;
                    a0=fmaf(w,r[0],a0); a1=fmaf(w,r[1],a1);
                    a2=fmaf(w,r[2],a2); a3=fmaf(w,r[3],a3);
                }
                float bdv=bd[du];
                float* ds=(float*)(sm+O_DS);
                ds[(g8*4+0)*33+du]=fmaxf(a0+bdv,0.f);
                ds[(g8*4+1)*33+du]=fmaxf(a1+bdv,0.f);
                ds[(g8*4+2)*33+du]=fmaxf(a2+bdv,0.f);
                ds[(g8*4+3)*33+du]=fmaxf(a3+bdv,0.f);
            }
            __syncthreads();
            if(tid<64){
                int bt=tid>>1, t2=tid&1;
                const float* ds=(const float*)(sm+O_DS);
                float acc=0.f;
#pragma unroll
                for(int k=0;k<32;k++) acc=fmaf(ds[bt*33+k],Wf[t2*32+k],acc);
                float pr=acc+bfv[t2]+ob[t2];
                out[(size_t)(b0+bt)*S_*2+(size_t)tt0*2+t2]=pr;
                put3(sm+O_B1,KP1,bt,3*(14+t2),pr);
            }
            __syncthreads();
        }
    }
}

extern "C" void kernel_launch(void* const* d_in, const int* in_sizes, int n_in,
                              void* d_out, int out_size){
    (void)in_sizes;(void)n_in;(void)out_size;
    prep<<<64,256>>>((const float*)d_in[2],(const float*)d_in[3],
                     (const float*)d_in[4],(const float*)d_in[5],
                     (const float*)d_in[6],(const float*)d_in[7],
                     (const float*)d_in[8],(const float*)d_in[9]);
    cudaFuncSetAttribute(lstm_tc,cudaFuncAttributeMaxDynamicSharedMemorySize,SMEMB);
    lstm_tc<<<128,256,SMEMB>>>((const float*)d_in[0],(const float*)d_in[1],
                               (const float*)d_in[10],(const float*)d_in[11],
                               (const float*)d_in[12],(const float*)d_in[13],
                               (const float*)d_in[14],(float*)d_out);
}